// round 6
// baseline (speedup 1.0000x reference)
#include <cuda_runtime.h>
#include <cuda_bf16.h>
#include <cstdint>

// Statically zero-initialized accumulators; last block resets them after
// writing the output so graph replays are deterministic.
__device__ double             g_total  = 0.0;
__device__ unsigned long long g_chunks = 0ull;   // active float4-chunks (rows*128)
__device__ unsigned int       g_done   = 0u;

#define THREADS 256
#define BLOCKS  1184   // 148 SMs * 8 blocks

// Chunk-parallel: one thread per float4 (row = idx>>7, chunk = idx&127).
// A warp's 32 consecutive chunks lie in one row -> label load is warp-uniform.
// Rows with label >= num_old are skipped (no embedding traffic).
__global__ __launch_bounds__(THREADS)
void fused_mse_kernel(const float* __restrict__ emb,
                      const float* __restrict__ cen,
                      const int*   __restrict__ labels,
                      const int*   __restrict__ num_old_p,
                      int batch,
                      float* __restrict__ out)
{
    const int num_old      = *num_old_p;
    const unsigned total   = (unsigned)batch * 128u;          // 8.4M float4 chunks
    const unsigned stride  = (unsigned)gridDim.x * THREADS;
    unsigned idx           = blockIdx.x * THREADS + threadIdx.x;

    const float4* __restrict__ emb4 = reinterpret_cast<const float4*>(emb);
    const float4* __restrict__ cen4 = reinterpret_cast<const float4*>(cen);

    float    acc = 0.0f;
    unsigned cnt = 0u;   // active chunks handled by this thread

    #pragma unroll 4
    for (; idx < total; idx += stride) {
        const unsigned row   = idx >> 7;
        const unsigned chunk = idx & 127u;
        const int      label = labels[row];          // warp-uniform broadcast
        if (label < num_old) {
            float4 ev = __ldcs(emb4 + idx);
            float4 cv = cen4[(unsigned)label * 128u + chunk];
            float d;
            d = ev.x - cv.x; acc = fmaf(d, d, acc);
            d = ev.y - cv.y; acc = fmaf(d, d, acc);
            d = ev.z - cv.z; acc = fmaf(d, d, acc);
            d = ev.w - cv.w; acc = fmaf(d, d, acc);
            cnt++;
        }
    }

    // Warp reduce.
    #pragma unroll
    for (int off = 16; off > 0; off >>= 1) {
        acc += __shfl_xor_sync(0xFFFFFFFFu, acc, off);
        cnt += __shfl_xor_sync(0xFFFFFFFFu, cnt, off);
    }

    __shared__ double       s_total;
    __shared__ unsigned int s_cnt;
    if (threadIdx.x == 0) { s_total = 0.0; s_cnt = 0u; }
    __syncthreads();

    if ((threadIdx.x & 31) == 0 && (acc != 0.0f || cnt != 0u)) {
        atomicAdd(&s_total, (double)acc);
        atomicAdd(&s_cnt, cnt);
    }
    __syncthreads();

    if (threadIdx.x == 0) {
        if (s_cnt != 0u || s_total != 0.0) {
            atomicAdd(&g_total, s_total);
            atomicAdd(&g_chunks, (unsigned long long)s_cnt);
        }
        __threadfence();
        unsigned int ticket = atomicAdd(&g_done, 1u);
        if (ticket == gridDim.x - 1u) {
            const double             t = g_total * (1.0 / 512.0);
            const unsigned long long c = g_chunks / 128ull;    // active rows
            out[0] = (c == 0ull) ? (float)t : (float)(t / (double)c);
            g_total  = 0.0;
            g_chunks = 0ull;
            g_done   = 0u;
        }
    }
}

extern "C" void kernel_launch(void* const* d_in, const int* in_sizes, int n_in,
                              void* d_out, int out_size)
{
    const float* emb       = (const float*)d_in[0];
    const float* cen       = (const float*)d_in[1];
    const int*   labels    = (const int*)d_in[2];
    const int*   num_old_p = (const int*)d_in[3];
    float*       out       = (float*)d_out;

    const int dim   = 512;
    const int batch = in_sizes[0] / dim;   // 65536

    fused_mse_kernel<<<BLOCKS, THREADS>>>(emb, cen, labels, num_old_p, batch, out);
}

// round 7
// speedup vs baseline: 1.0118x; 1.0118x over previous
#include <cuda_runtime.h>
#include <cuda_bf16.h>
#include <cstdint>

__device__ double             g_total  = 0.0;
__device__ unsigned long long g_chunks = 0ull;   // active float4-chunks (rows*128)
__device__ unsigned int       g_done   = 0u;

#define THREADS 256
#define BLOCKS  1184   // 148 SMs * 8

__global__ __launch_bounds__(THREADS)
void fused_mse_kernel(const float* __restrict__ emb,
                      const float* __restrict__ cen,
                      const int*   __restrict__ labels,
                      const int*   __restrict__ num_old_p,
                      int batch,
                      float* __restrict__ out)
{
    const int      num_old = *num_old_p;
    const unsigned total   = (unsigned)batch * 128u;        // float4 chunks
    const unsigned stride  = (unsigned)gridDim.x * THREADS;
    unsigned       i       = blockIdx.x * THREADS + threadIdx.x;

    const float4* __restrict__ emb4 = reinterpret_cast<const float4*>(emb);
    const float4* __restrict__ cen4 = reinterpret_cast<const float4*>(cen);

    const float4 z4 = make_float4(0.f, 0.f, 0.f, 0.f);

    float    acc = 0.0f;
    unsigned cnt = 0u;

    // 4-deep software pipeline: all labels -> all predicates -> all loads
    // (predicated, branch-free) -> all FMAs. Guarantees 8 loads in flight
    // per thread regardless of how ptxas schedules guarded bodies.
    for (; i + 3u * stride < total; i += 4u * stride) {
        const unsigned i0 = i, i1 = i + stride, i2 = i + 2u * stride, i3 = i + 3u * stride;

        const int l0 = labels[i0 >> 7];
        const int l1 = labels[i1 >> 7];
        const int l2 = labels[i2 >> 7];
        const int l3 = labels[i3 >> 7];

        const bool a0 = l0 < num_old;
        const bool a1 = l1 < num_old;
        const bool a2 = l2 < num_old;
        const bool a3 = l3 < num_old;

        // Labels are always in [0, 1000): cen addresses are in-bounds even
        // when inactive; predication only suppresses the traffic.
        const float4 e0 = a0 ? __ldcs(emb4 + i0) : z4;
        const float4 c0 = a0 ? cen4[(unsigned)l0 * 128u + (i0 & 127u)] : z4;
        const float4 e1 = a1 ? __ldcs(emb4 + i1) : z4;
        const float4 c1 = a1 ? cen4[(unsigned)l1 * 128u + (i1 & 127u)] : z4;
        const float4 e2 = a2 ? __ldcs(emb4 + i2) : z4;
        const float4 c2 = a2 ? cen4[(unsigned)l2 * 128u + (i2 & 127u)] : z4;
        const float4 e3 = a3 ? __ldcs(emb4 + i3) : z4;
        const float4 c3 = a3 ? cen4[(unsigned)l3 * 128u + (i3 & 127u)] : z4;

        float d;
        d = e0.x - c0.x; acc = fmaf(d, d, acc);
        d = e0.y - c0.y; acc = fmaf(d, d, acc);
        d = e0.z - c0.z; acc = fmaf(d, d, acc);
        d = e0.w - c0.w; acc = fmaf(d, d, acc);
        d = e1.x - c1.x; acc = fmaf(d, d, acc);
        d = e1.y - c1.y; acc = fmaf(d, d, acc);
        d = e1.z - c1.z; acc = fmaf(d, d, acc);
        d = e1.w - c1.w; acc = fmaf(d, d, acc);
        d = e2.x - c2.x; acc = fmaf(d, d, acc);
        d = e2.y - c2.y; acc = fmaf(d, d, acc);
        d = e2.z - c2.z; acc = fmaf(d, d, acc);
        d = e2.w - c2.w; acc = fmaf(d, d, acc);
        d = e3.x - c3.x; acc = fmaf(d, d, acc);
        d = e3.y - c3.y; acc = fmaf(d, d, acc);
        d = e3.z - c3.z; acc = fmaf(d, d, acc);
        d = e3.w - c3.w; acc = fmaf(d, d, acc);

        cnt += (unsigned)a0 + (unsigned)a1 + (unsigned)a2 + (unsigned)a3;
    }

    // Remainder (<= 4 strided iterations).
    for (; i < total; i += stride) {
        const int label = labels[i >> 7];
        if (label < num_old) {
            const float4 ev = __ldcs(emb4 + i);
            const float4 cv = cen4[(unsigned)label * 128u + (i & 127u)];
            float d;
            d = ev.x - cv.x; acc = fmaf(d, d, acc);
            d = ev.y - cv.y; acc = fmaf(d, d, acc);
            d = ev.z - cv.z; acc = fmaf(d, d, acc);
            d = ev.w - cv.w; acc = fmaf(d, d, acc);
            cnt++;
        }
    }

    // Warp reduce.
    #pragma unroll
    for (int off = 16; off > 0; off >>= 1) {
        acc += __shfl_xor_sync(0xFFFFFFFFu, acc, off);
        cnt += __shfl_xor_sync(0xFFFFFFFFu, cnt, off);
    }

    __shared__ double       s_total;
    __shared__ unsigned int s_cnt;
    if (threadIdx.x == 0) { s_total = 0.0; s_cnt = 0u; }
    __syncthreads();

    if ((threadIdx.x & 31) == 0 && (acc != 0.0f || cnt != 0u)) {
        atomicAdd(&s_total, (double)acc);
        atomicAdd(&s_cnt, cnt);
    }
    __syncthreads();

    if (threadIdx.x == 0) {
        if (s_cnt != 0u || s_total != 0.0) {
            atomicAdd(&g_total, s_total);
            atomicAdd(&g_chunks, (unsigned long long)s_cnt);
        }
        __threadfence();
        unsigned int ticket = atomicAdd(&g_done, 1u);
        if (ticket == gridDim.x - 1u) {
            const double             t = g_total * (1.0 / 512.0);
            const unsigned long long c = g_chunks / 128ull;    // active rows
            out[0] = (c == 0ull) ? (float)t : (float)(t / (double)c);
            g_total  = 0.0;
            g_chunks = 0ull;
            g_done   = 0u;
        }
    }
}

extern "C" void kernel_launch(void* const* d_in, const int* in_sizes, int n_in,
                              void* d_out, int out_size)
{
    const float* emb       = (const float*)d_in[0];
    const float* cen       = (const float*)d_in[1];
    const int*   labels    = (const int*)d_in[2];
    const int*   num_old_p = (const int*)d_in[3];
    float*       out       = (float*)d_out;

    const int dim   = 512;
    const int batch = in_sizes[0] / dim;   // 65536

    fused_mse_kernel<<<BLOCKS, THREADS>>>(emb, cen, labels, num_old_p, batch, out);
}

// round 8
// speedup vs baseline: 1.2052x; 1.1911x over previous
#include <cuda_runtime.h>
#include <cuda_bf16.h>
#include <cstdint>

__device__ double             g_total = 0.0;
__device__ unsigned long long g_rows  = 0ull;
__device__ unsigned int       g_done  = 0u;

#define THREADS 256
#define BLOCKS  592   // 148 SMs * 4

// Packed f32x2 FMA (sm_103a FFMA2 — PTX-only).
__device__ __forceinline__ unsigned long long fma2(unsigned long long a,
                                                   unsigned long long b,
                                                   unsigned long long c)
{
    unsigned long long d;
    asm("fma.rn.f32x2 %0, %1, %2, %3;" : "=l"(d) : "l"(a), "l"(b), "l"(c));
    return d;
}

__device__ __forceinline__ float unpack_sum(unsigned long long v)
{
    return __int_as_float((int)(v & 0xFFFFFFFFull)) +
           __int_as_float((int)(v >> 32));
}

__global__ __launch_bounds__(THREADS)
void fused_mse_kernel(const float* __restrict__ emb,
                      const float* __restrict__ cen,
                      const int*   __restrict__ labels,
                      const int*   __restrict__ num_old_p,
                      int batch, int rows_per_block,
                      float* __restrict__ out)
{
    const int num_old = *num_old_p;

    __shared__ unsigned int s_list[256];   // packed: row | (label<<16)
    __shared__ unsigned int s_cnt;
    __shared__ unsigned int s_warpbase[THREADS / 32];
    __shared__ double       s_total;

    if (threadIdx.x == 0) { s_cnt = 0u; s_total = 0.0; }
    __syncthreads();

    // ---- Per-block compaction of this block's row slice ----
    const int row0  = blockIdx.x * rows_per_block;
    int nrows = batch - row0;
    if (nrows > rows_per_block) nrows = rows_per_block;
    if (nrows < 0) nrows = 0;

    {
        const int  tid    = threadIdx.x;
        const int  lane   = tid & 31;
        const int  wid    = tid >> 5;
        bool       active = false;
        int        label  = 0;
        const int  row    = row0 + tid;
        if (tid < nrows) { label = labels[row]; active = (label < num_old); }
        const unsigned mask = __ballot_sync(0xFFFFFFFFu, active);
        if (lane == 0) s_warpbase[wid] = atomicAdd(&s_cnt, (unsigned)__popc(mask));
        __syncwarp();
        if (active) {
            const unsigned pos = s_warpbase[wid] + (unsigned)__popc(mask & ((1u << lane) - 1u));
            s_list[pos] = (unsigned)row | ((unsigned)label << 16);
        }
    }
    __syncthreads();

    const unsigned M  = s_cnt;          // active rows in this block
    const unsigned Mc = M * 128u;       // float4 chunks to process

    const double2* __restrict__ emb2 = reinterpret_cast<const double2*>(emb);
    const double2* __restrict__ cen2 = reinterpret_cast<const double2*>(cen);

    const unsigned long long NEG1 = 0xBF800000BF800000ull;   // (-1.0f, -1.0f)
    unsigned long long accA = 0ull, accB = 0ull, accC = 0ull, accD = 0ull;
    const double2 Z2 = make_double2(0.0, 0.0);

    // ---- Hot loop: depth-4 batched pipeline over compacted chunks ----
    // Slot k handles chunk j = i + k*THREADS. Warp-uniform s_list reads
    // (32 consecutive chunks lie in one 128-chunk row).
    for (unsigned i = threadIdx.x; i < Mc; i += 4u * THREADS) {
        const unsigned j0 = i;
        const unsigned j1 = i + THREADS;
        const unsigned j2 = i + 2u * THREADS;
        const unsigned j3 = i + 3u * THREADS;
        const bool b1 = j1 < Mc, b2 = j2 < Mc, b3 = j3 < Mc;
        const unsigned k1 = b1 ? j1 : 0u;
        const unsigned k2 = b2 ? j2 : 0u;
        const unsigned k3 = b3 ? j3 : 0u;

        const unsigned p0 = s_list[j0 >> 7];
        const unsigned p1 = s_list[k1 >> 7];
        const unsigned p2 = s_list[k2 >> 7];
        const unsigned p3 = s_list[k3 >> 7];

        const unsigned e_i0 = (p0 & 0xFFFFu) * 128u + (j0 & 127u);
        const unsigned c_i0 = (p0 >> 16)     * 128u + (j0 & 127u);
        const unsigned e_i1 = (p1 & 0xFFFFu) * 128u + (k1 & 127u);
        const unsigned c_i1 = (p1 >> 16)     * 128u + (k1 & 127u);
        const unsigned e_i2 = (p2 & 0xFFFFu) * 128u + (k2 & 127u);
        const unsigned c_i2 = (p2 >> 16)     * 128u + (k2 & 127u);
        const unsigned e_i3 = (p3 & 0xFFFFu) * 128u + (k3 & 127u);
        const unsigned c_i3 = (p3 >> 16)     * 128u + (k3 & 127u);

        // All 8 loads issued before any consumption.
        const double2 e0 = __ldcs(emb2 + e_i0);
        const double2 c0 = cen2[c_i0];
        const double2 e1 = b1 ? __ldcs(emb2 + e_i1) : Z2;
        const double2 c1 = b1 ? cen2[c_i1] : Z2;
        const double2 e2 = b2 ? __ldcs(emb2 + e_i2) : Z2;
        const double2 c2 = b2 ? cen2[c_i2] : Z2;
        const double2 e3 = b3 ? __ldcs(emb2 + e_i3) : Z2;
        const double2 c3 = b3 ? cen2[c_i3] : Z2;

        // diff = e - c via packed fma(c, -1, e); acc += diff*diff.
        unsigned long long d;
        d = fma2(__double_as_longlong(c0.x), NEG1, __double_as_longlong(e0.x)); accA = fma2(d, d, accA);
        d = fma2(__double_as_longlong(c0.y), NEG1, __double_as_longlong(e0.y)); accB = fma2(d, d, accB);
        d = fma2(__double_as_longlong(c1.x), NEG1, __double_as_longlong(e1.x)); accC = fma2(d, d, accC);
        d = fma2(__double_as_longlong(c1.y), NEG1, __double_as_longlong(e1.y)); accD = fma2(d, d, accD);
        d = fma2(__double_as_longlong(c2.x), NEG1, __double_as_longlong(e2.x)); accA = fma2(d, d, accA);
        d = fma2(__double_as_longlong(c2.y), NEG1, __double_as_longlong(e2.y)); accB = fma2(d, d, accB);
        d = fma2(__double_as_longlong(c3.x), NEG1, __double_as_longlong(e3.x)); accC = fma2(d, d, accC);
        d = fma2(__double_as_longlong(c3.y), NEG1, __double_as_longlong(e3.y)); accD = fma2(d, d, accD);
    }

    // ---- Reduction ----
    float acc = unpack_sum(accA) + unpack_sum(accB) +
                unpack_sum(accC) + unpack_sum(accD);
    #pragma unroll
    for (int off = 16; off > 0; off >>= 1)
        acc += __shfl_xor_sync(0xFFFFFFFFu, acc, off);

    if ((threadIdx.x & 31) == 0 && acc != 0.0f)
        atomicAdd(&s_total, (double)acc);
    __syncthreads();

    if (threadIdx.x == 0) {
        if (s_total != 0.0) atomicAdd(&g_total, s_total);
        if (M != 0u)        atomicAdd(&g_rows, (unsigned long long)M);
        __threadfence();
        const unsigned ticket = atomicAdd(&g_done, 1u);
        if (ticket == gridDim.x - 1u) {
            const double             t = g_total * (1.0 / 512.0);
            const unsigned long long c = g_rows;
            out[0] = (c == 0ull) ? (float)t : (float)(t / (double)c);
            g_total = 0.0;
            g_rows  = 0ull;
            g_done  = 0u;
        }
    }
}

extern "C" void kernel_launch(void* const* d_in, const int* in_sizes, int n_in,
                              void* d_out, int out_size)
{
    const float* emb       = (const float*)d_in[0];
    const float* cen       = (const float*)d_in[1];
    const int*   labels    = (const int*)d_in[2];
    const int*   num_old_p = (const int*)d_in[3];
    float*       out       = (float*)d_out;

    const int dim   = 512;
    const int batch = in_sizes[0] / dim;                 // 65536
    const int rows_per_block = (batch + BLOCKS - 1) / BLOCKS;   // 111

    fused_mse_kernel<<<BLOCKS, THREADS>>>(emb, cen, labels, num_old_p,
                                          batch, rows_per_block, out);
}

// round 9
// speedup vs baseline: 1.2909x; 1.0711x over previous
#include <cuda_runtime.h>
#include <cuda_bf16.h>
#include <cstdint>

__device__ double             g_total = 0.0;
__device__ unsigned long long g_rows  = 0ull;
__device__ unsigned int       g_done  = 0u;

#define THREADS 256
#define BLOCKS  888   // 148 SMs * 6

// Packed f32x2 FMA (sm_103a FFMA2 — PTX-only).
__device__ __forceinline__ unsigned long long fma2(unsigned long long a,
                                                   unsigned long long b,
                                                   unsigned long long c)
{
    unsigned long long d;
    asm("fma.rn.f32x2 %0, %1, %2, %3;" : "=l"(d) : "l"(a), "l"(b), "l"(c));
    return d;
}

__device__ __forceinline__ float unpack_sum(unsigned long long v)
{
    return __int_as_float((int)(v & 0xFFFFFFFFull)) +
           __int_as_float((int)(v >> 32));
}

__global__ __launch_bounds__(THREADS, 6)
void fused_mse_kernel(const float* __restrict__ emb,
                      const float* __restrict__ cen,
                      const int*   __restrict__ labels,
                      const int*   __restrict__ num_old_p,
                      int batch, int rows_per_block,
                      float* __restrict__ out)
{
    const int num_old = *num_old_p;

    __shared__ unsigned int s_list[128];   // packed: row | (label<<16); M <= 74
    __shared__ unsigned int s_cnt;
    __shared__ unsigned int s_warpbase[THREADS / 32];
    __shared__ double       s_total;

    if (threadIdx.x == 0) { s_cnt = 0u; s_total = 0.0; }
    __syncthreads();

    // ---- Per-block compaction of this block's row slice ----
    const int row0  = blockIdx.x * rows_per_block;
    int nrows = batch - row0;
    if (nrows > rows_per_block) nrows = rows_per_block;
    if (nrows < 0) nrows = 0;

    {
        const int  tid    = threadIdx.x;
        const int  lane   = tid & 31;
        const int  wid    = tid >> 5;
        bool       active = false;
        int        label  = 0;
        const int  row    = row0 + tid;
        if (tid < nrows) { label = labels[row]; active = (label < num_old); }
        const unsigned mask = __ballot_sync(0xFFFFFFFFu, active);
        if (lane == 0) s_warpbase[wid] = atomicAdd(&s_cnt, (unsigned)__popc(mask));
        __syncwarp();
        if (active) {
            const unsigned pos = s_warpbase[wid] + (unsigned)__popc(mask & ((1u << lane) - 1u));
            s_list[pos] = (unsigned)row | ((unsigned)label << 16);
        }
    }
    __syncthreads();

    const unsigned M  = s_cnt;          // active rows in this block
    const unsigned Mc = M * 128u;       // double2 chunks (128 per row)

    const double2* __restrict__ emb2 = reinterpret_cast<const double2*>(emb);
    const double2* __restrict__ cen2 = reinterpret_cast<const double2*>(cen);

    const unsigned long long NEG1 = 0xBF800000BF800000ull;   // (-1.0f, -1.0f)
    unsigned long long accA = 0ull, accB = 0ull, accC = 0ull, accD = 0ull;

    unsigned i = threadIdx.x;

    // ---- Steady state: no guards, 8 loads batched before consumption ----
    for (; i + 3u * THREADS < Mc; i += 4u * THREADS) {
        const unsigned j0 = i;
        const unsigned j1 = i + THREADS;
        const unsigned j2 = i + 2u * THREADS;
        const unsigned j3 = i + 3u * THREADS;

        const unsigned p0 = s_list[j0 >> 7];
        const unsigned p1 = s_list[j1 >> 7];
        const unsigned p2 = s_list[j2 >> 7];
        const unsigned p3 = s_list[j3 >> 7];

        const unsigned e_i0 = (p0 & 0xFFFFu) * 128u + (j0 & 127u);
        const unsigned c_i0 = (p0 >> 16)     * 128u + (j0 & 127u);
        const unsigned e_i1 = (p1 & 0xFFFFu) * 128u + (j1 & 127u);
        const unsigned c_i1 = (p1 >> 16)     * 128u + (j1 & 127u);
        const unsigned e_i2 = (p2 & 0xFFFFu) * 128u + (j2 & 127u);
        const unsigned c_i2 = (p2 >> 16)     * 128u + (j2 & 127u);
        const unsigned e_i3 = (p3 & 0xFFFFu) * 128u + (j3 & 127u);
        const unsigned c_i3 = (p3 >> 16)     * 128u + (j3 & 127u);

        const double2 e0 = __ldcs(emb2 + e_i0);
        const double2 c0 = cen2[c_i0];
        const double2 e1 = __ldcs(emb2 + e_i1);
        const double2 c1 = cen2[c_i1];
        const double2 e2 = __ldcs(emb2 + e_i2);
        const double2 c2 = cen2[c_i2];
        const double2 e3 = __ldcs(emb2 + e_i3);
        const double2 c3 = cen2[c_i3];

        unsigned long long d;
        d = fma2(__double_as_longlong(c0.x), NEG1, __double_as_longlong(e0.x)); accA = fma2(d, d, accA);
        d = fma2(__double_as_longlong(c0.y), NEG1, __double_as_longlong(e0.y)); accB = fma2(d, d, accB);
        d = fma2(__double_as_longlong(c1.x), NEG1, __double_as_longlong(e1.x)); accC = fma2(d, d, accC);
        d = fma2(__double_as_longlong(c1.y), NEG1, __double_as_longlong(e1.y)); accD = fma2(d, d, accD);
        d = fma2(__double_as_longlong(c2.x), NEG1, __double_as_longlong(e2.x)); accA = fma2(d, d, accA);
        d = fma2(__double_as_longlong(c2.y), NEG1, __double_as_longlong(e2.y)); accB = fma2(d, d, accB);
        d = fma2(__double_as_longlong(c3.x), NEG1, __double_as_longlong(e3.x)); accC = fma2(d, d, accC);
        d = fma2(__double_as_longlong(c3.y), NEG1, __double_as_longlong(e3.y)); accD = fma2(d, d, accD);
    }

    // ---- Remainder: <= 4 guarded strided iterations ----
    for (; i < Mc; i += THREADS) {
        const unsigned p  = s_list[i >> 7];
        const double2  ev = __ldcs(emb2 + ((p & 0xFFFFu) * 128u + (i & 127u)));
        const double2  cv = cen2[(p >> 16) * 128u + (i & 127u)];
        unsigned long long d;
        d = fma2(__double_as_longlong(cv.x), NEG1, __double_as_longlong(ev.x)); accA = fma2(d, d, accA);
        d = fma2(__double_as_longlong(cv.y), NEG1, __double_as_longlong(ev.y)); accB = fma2(d, d, accB);
    }

    // ---- Reduction ----
    float acc = unpack_sum(accA) + unpack_sum(accB) +
                unpack_sum(accC) + unpack_sum(accD);
    #pragma unroll
    for (int off = 16; off > 0; off >>= 1)
        acc += __shfl_xor_sync(0xFFFFFFFFu, acc, off);

    if ((threadIdx.x & 31) == 0 && acc != 0.0f)
        atomicAdd(&s_total, (double)acc);
    __syncthreads();

    if (threadIdx.x == 0) {
        if (s_total != 0.0) atomicAdd(&g_total, s_total);
        if (M != 0u)        atomicAdd(&g_rows, (unsigned long long)M);
        __threadfence();
        const unsigned ticket = atomicAdd(&g_done, 1u);
        if (ticket == gridDim.x - 1u) {
            const double             t = g_total * (1.0 / 512.0);
            const unsigned long long c = g_rows;
            out[0] = (c == 0ull) ? (float)t : (float)(t / (double)c);
            g_total = 0.0;
            g_rows  = 0ull;
            g_done  = 0u;
        }
    }
}

extern "C" void kernel_launch(void* const* d_in, const int* in_sizes, int n_in,
                              void* d_out, int out_size)
{
    const float* emb       = (const float*)d_in[0];
    const float* cen       = (const float*)d_in[1];
    const int*   labels    = (const int*)d_in[2];
    const int*   num_old_p = (const int*)d_in[3];
    float*       out       = (float*)d_out;

    const int dim   = 512;
    const int batch = in_sizes[0] / dim;                        // 65536
    const int rows_per_block = (batch + BLOCKS - 1) / BLOCKS;   // 74

    fused_mse_kernel<<<BLOCKS, THREADS>>>(emb, cen, labels, num_old_p,
                                          batch, rows_per_block, out);
}